// round 11
// baseline (speedup 1.0000x reference)
#include <cuda_runtime.h>
#include <cuda_bf16.h>
#include <cuda_fp8.h>
#include <stdint.h>

#define NS     512
#define NU     64
#define DIM    1024
#define NROWS  (NS*NU)         // 32768
#define EPSV   1e-6f
#define BM     128
#define BN     128
#define NSPLIT (NS/BN)         // 4
#define KC     128
#define NSTAGE (DIM/KC)        // 8
#define STG_BYTES 32768        // A 16KB + B 16KB
#define NBUF   2
#define LOG2E  1.4426950408889634f
#define LN2    0.6931471805599453f
#define SMEM_DYN (NBUF*STG_BYTES + 1024 + 2048)

// ---------------- device scratch ----------------
// stage-major, PRE-SWIZZLED (SW128) fp8 operands: one contiguous 16KB tile
// per (stage, 128-row block) -> single cp.async.bulk per operand per stage.
__device__ uint8_t g_A8s[(size_t)NSTAGE*NROWS*KC];  // 32 MB
__device__ uint8_t g_C8s[(size_t)NSTAGE*NS*KC];     // 512 KB
__device__ float  g_cs[NROWS];                      // cos_self (exact fp32)
__device__ float  g_ps[NSPLIT*(size_t)NROWS];       // partial softmax sums
__device__ double g_loss;

// ---------------- helpers ----------------
__device__ __forceinline__ uint32_t smem_u32(const void* p) {
    uint32_t a;
    asm("{ .reg .u64 t; cvta.to.shared.u64 t, %1; cvt.u32.u64 %0, t; }"
        : "=r"(a) : "l"(p));
    return a;
}
__device__ __forceinline__ uint32_t sw128(uint32_t off) {
    return off ^ ((off >> 3) & 0x70);
}
#define BULK_G2S(dst, src, bytes, mbar) \
    asm volatile("cp.async.bulk.shared::cluster.global.mbarrier::complete_tx::bytes " \
                 "[%0], [%1], %2, [%3];" \
                 :: "r"(dst), "l"(src), "r"(bytes), "r"(mbar) : "memory")
#define MBAR_INIT(mb, cnt) \
    asm volatile("mbarrier.init.shared.b64 [%0], %1;" :: "r"(mb), "r"(cnt) : "memory")
#define MBAR_EXPECT_TX(mb, tx) \
    asm volatile("mbarrier.arrive.expect_tx.shared.b64 _, [%0], %1;" \
                 :: "r"(mb), "r"(tx) : "memory")
#define MBAR_WAIT(mb, ph) do { \
    uint32_t _m = (mb), _p = (ph), _d; \
    asm volatile("{\n\t.reg .pred p;\n\t" \
        "mbarrier.try_wait.parity.shared.b64 p, [%1], %2;\n\t" \
        "selp.b32 %0, 1, 0, p;\n\t}" : "=r"(_d) : "r"(_m), "r"(_p) : "memory"); \
    if (!_d) { \
        asm volatile("{\n\t.reg .pred P1;\n\tWL%=:\n\t" \
            "mbarrier.try_wait.parity.shared.b64 P1, [%0], %1;\n\t" \
            "@P1 bra.uni WD%=;\n\tbra.uni WL%=;\n\tWD%=:\n\t}" \
            :: "r"(_m), "r"(_p) : "memory"); \
    } } while (0)
#define LDSM4(r0, r1, r2, r3, addr) \
    asm volatile("ldmatrix.sync.aligned.m8n8.x4.shared.b16 {%0,%1,%2,%3}, [%4];" \
        : "=r"(r0), "=r"(r1), "=r"(r2), "=r"(r3) : "r"(addr))
#define MMA8(c, a, b0, b1) \
    asm volatile("mma.sync.aligned.m16n8k32.row.col.f32.e4m3.e4m3.f32 " \
        "{%0,%1,%2,%3},{%4,%5,%6,%7},{%8,%9},{%0,%1,%2,%3};" \
        : "+f"((c)[0]), "+f"((c)[1]), "+f"((c)[2]), "+f"((c)[3]) \
        : "r"((a)[0]), "r"((a)[1]), "r"((a)[2]), "r"((a)[3]), "r"(b0), "r"(b1))

// FMA-only 2^z (no MUFU): rel err ~2e-6
__device__ __forceinline__ float exp2_fast(float z) {
    float kf = z + 12582912.0f;            // 1.5 * 2^23
    int   ki = __float_as_int(kf);
    float f  = z - (kf - 12582912.0f);     // f in [-0.5, 0.5]
    float p  = 1.33335581e-3f;
    p = fmaf(p, f, 9.61812910e-3f);
    p = fmaf(p, f, 5.55041087e-2f);
    p = fmaf(p, f, 2.40226507e-1f);
    p = fmaf(p, f, 6.93147181e-1f);
    p = fmaf(p, f, 1.0f);
    return __int_as_float(__float_as_int(p) + (ki << 23));
}

__device__ __forceinline__ uint32_t fp8x4(float4 v) {
    __nv_fp8x4_e4m3 r(v);
    return *(uint32_t*)&r;
}

// ---------------- kernel 1: centroids + row stats + fp8 quant (pre-swizzled)
// grid 512 (one speaker), 256 threads, 4 CTAs/SM target.
__global__ __launch_bounds__(256, 4)
void k_prep(const float* __restrict__ X) {
    __shared__ float smS[DIM];
    __shared__ float red[256];
    int n = blockIdx.x, t = threadIdx.x;
    if (n == 0 && t == 0) g_loss = 0.0;
    const float4* xn = (const float4*)(X + (size_t)n * NU * DIM);

    // ---- phase 1: accumulate speaker sum S (2 chains for MLP) ----
    float4 sa = make_float4(0.f, 0.f, 0.f, 0.f);
    float4 sb = make_float4(0.f, 0.f, 0.f, 0.f);
    #pragma unroll 8
    for (int m = 0; m < NU; m += 2) {
        float4 va = xn[m * 256 + t];
        float4 vb = xn[(m + 1) * 256 + t];
        sa.x += va.x; sa.y += va.y; sa.z += va.z; sa.w += va.w;
        sb.x += vb.x; sb.y += vb.y; sb.z += vb.z; sb.w += vb.w;
    }
    float4 s = make_float4(sa.x + sb.x, sa.y + sb.y, sa.z + sb.z, sa.w + sb.w);
    float4 mn = make_float4(s.x * (1.f/NU), s.y * (1.f/NU),
                            s.z * (1.f/NU), s.w * (1.f/NU));
    float ssl = mn.x*mn.x + mn.y*mn.y + mn.z*mn.z + mn.w*mn.w;
    red[t] = ssl;
    ((float4*)smS)[t] = s;
    __syncthreads();
    for (int o = 128; o > 0; o >>= 1) { if (t < o) red[t] += red[t + o]; __syncthreads(); }
    float inv = rsqrtf(fmaxf(red[0], EPSV));
    float SS = red[0] * 4096.f;                       // ||S||^2 exact

    // centroid fp8, stage-major + swizzled: stage = t>>5, chunk byte = 4*(t&31)
    {
        float sc = 16.f * inv;
        uint32_t pk = fp8x4(make_float4(mn.x*sc, mn.y*sc, mn.z*sc, mn.w*sc));
        size_t off = (size_t)(t >> 5) * (NS * (size_t)KC)
                   + sw128((uint32_t)n * 128u + 4u * (t & 31));
        *(uint32_t*)(g_C8s + off) = pk;
    }

    // ---- phase 2: per-row stats + quantized write (stage-major, swizzled) --
    int wid = t >> 5, lane = t & 31;
    #pragma unroll 1
    for (int r = 0; r < 8; ++r) {
        int m = wid * 8 + r;
        const float4* x = xn + m * 256;
        float4 v[8];
        float rx = 0.f, rs = 0.f;
        #pragma unroll
        for (int q = 0; q < 8; ++q) {
            v[q] = x[lane + 32 * q];
            float4 c = ((const float4*)smS)[lane + 32 * q];
            rx += v[q].x*v[q].x + v[q].y*v[q].y + v[q].z*v[q].z + v[q].w*v[q].w;
            rs += v[q].x*c.x + v[q].y*c.y + v[q].z*c.z + v[q].w*c.w;
        }
        #pragma unroll
        for (int o = 16; o > 0; o >>= 1) {
            rx += __shfl_xor_sync(0xffffffffu, rx, o);
            rs += __shfl_xor_sync(0xffffffffu, rs, o);
        }
        float inv_e = rsqrtf(fmaxf(rx, EPSV));
        int row = n * NU + m;
        if (lane == 0) {
            float xu = (rs - rx) * (1.f / 63.f);
            float uu = (SS - 2.f * rs + rx) * (1.f / 3969.f);
            g_cs[row] = xu * inv_e * rsqrtf(fmaxf(uu, EPSV));
        }
        float qs = 16.f * inv_e;
        uint32_t swoff = sw128((uint32_t)row * 128u + 4u * lane);
        #pragma unroll
        for (int q = 0; q < 8; ++q) {
            size_t off = (size_t)q * ((size_t)NROWS * KC) + swoff;
            *(uint32_t*)(g_A8s + off) =
                fp8x4(make_float4(v[q].x*qs, v[q].y*qs, v[q].z*qs, v[q].w*qs));
        }
    }
}

// ---------------- kernel 2: fp8 MMA GEMM, bulk pipeline, 3 CTAs/SM ----------
// grid (4, 256): x = col-split (128 cols), y = row-block (128 rows).
// 256 threads / 8 warps: 4 row-groups x 2 col-groups, warp tile 32x64.
__global__ __launch_bounds__(256, 3)
void k_gemm(const float* __restrict__ wp, const float* __restrict__ bp) {
    extern __shared__ char smraw[];
    __shared__ __align__(8) uint64_t mbars[NBUF];
    uint32_t raw  = smem_u32(smraw);
    uint32_t base = (raw + 1023u) & ~1023u;
    float* sm_s   = (float*)(smraw + (base - raw) + NBUF * STG_BYTES);
    uint32_t mb0  = smem_u32(mbars);

    int tid = threadIdx.x, lane = tid & 31, wid = tid >> 5;
    int wr = wid & 3, wc = wid >> 2;      // 4 row-groups x 2 col-groups
    int c0 = blockIdx.x * BN, r0 = blockIdx.y * BM;

    if (tid == 0) {
        MBAR_INIT(mb0,     1);
        MBAR_INIT(mb0 + 8, 1);
    }
    __syncthreads();

    float acc[2][8][4];
    #pragma unroll
    for (int i = 0; i < 2; ++i)
        #pragma unroll
        for (int j = 0; j < 8; ++j)
            #pragma unroll
            for (int q = 0; q < 4; ++q) acc[i][j][q] = 0.f;

    const char* abase = (const char*)g_A8s + (size_t)r0 * KC;
    const char* bbase = (const char*)g_C8s + (size_t)c0 * KC;

    auto load_stage = [&](int s) {
        int buf = s & 1;
        uint32_t mb = mb0 + 8u * (uint32_t)buf;
        uint32_t sb = base + (uint32_t)buf * STG_BYTES;
        MBAR_EXPECT_TX(mb, STG_BYTES);
        BULK_G2S(sb,          abase + (size_t)s * ((size_t)NROWS * KC), 16384u, mb);
        BULK_G2S(sb + 16384u, bbase + (size_t)s * ((size_t)NS * KC),    16384u, mb);
    };

    // ---- mma over one staged KC=128 slab (4 x k32 steps) ----
    auto mma_stage = [&](int buf) {
        uint32_t ab = base + (uint32_t)buf * STG_BYTES;
        uint32_t bb = ab + 16384u;
        int arow = wr * 32 + (lane & 15);
        uint32_t aX = (uint32_t)(arow & 7) * 16u;
        uint32_t arb = ab + (uint32_t)arow * 128u;
        int nrl = wc * 64 + (lane & 7) + ((lane >> 4) << 3);
        uint32_t bX = (uint32_t)(nrl & 7) * 16u;
        uint32_t brb = bb + (uint32_t)nrl * 128u;
        #pragma unroll
        for (int ks = 0; ks < 4; ++ks) {
            uint32_t acb = ((uint32_t)(ks * 32 + ((lane >> 4) << 4))) ^ aX;
            uint32_t bcb = ((uint32_t)(ks * 32 + (((lane >> 3) & 1) << 4))) ^ bX;
            uint32_t a[2][4];
            LDSM4(a[0][0], a[0][1], a[0][2], a[0][3], arb + acb);
            LDSM4(a[1][0], a[1][1], a[1][2], a[1][3], arb + 16u * 128u + acb);
            #pragma unroll
            for (int g = 0; g < 4; ++g) {
                uint32_t b0, b1, b2, b3;
                LDSM4(b0, b1, b2, b3, brb + (uint32_t)g * (16u * 128u) + bcb);
                MMA8(acc[0][2 * g    ], a[0], b0, b1);
                MMA8(acc[0][2 * g + 1], a[0], b2, b3);
                MMA8(acc[1][2 * g    ], a[1], b0, b1);
                MMA8(acc[1][2 * g + 1], a[1], b2, b3);
            }
        }
    };

    // ---- 2-buffer bulk pipeline (lookahead 1) ----
    if (tid == 0) load_stage(0);
    for (int s = 0; s < NSTAGE; ++s) {
        MBAR_WAIT(mb0 + 8u * (uint32_t)(s & 1), (s >> 1) & 1);
        __syncthreads();           // all warps done with mma(s-1); buf free
        if (tid == 0 && s + 1 < NSTAGE) load_stage(s + 1);
        mma_stage(s & 1);
    }
    __syncthreads();

    // ---- epilogue: base-2 softmax partial sums; cos = acc / 256 ----
    const float wv = *wp, bv = *bp;
    const float b2 = bv * LOG2E;
    const float scal2 = wv * LOG2E * (1.f / 256.f);
    #pragma unroll
    for (int mi = 0; mi < 2; ++mi)
        #pragma unroll
        for (int h = 0; h < 2; ++h) {
            int rl = wr * 32 + mi * 16 + (lane >> 2) + h * 8;
            int grow = r0 + rl, nself = grow >> 6;
            float zpos = fmaf(wv * LOG2E, g_cs[grow], b2);
            float sum = 0.f;
            #pragma unroll
            for (int ni = 0; ni < 8; ++ni)
                #pragma unroll
                for (int j = 0; j < 2; ++j) {
                    int cg = c0 + wc * 64 + ni * 8 + (lane & 3) * 2 + j;
                    float z = fmaf(acc[mi][ni][h * 2 + j], scal2, b2);
                    if (cg == nself) z = zpos;
                    sum += exp2_fast(z);
                }
            sum += __shfl_xor_sync(0xffffffffu, sum, 1);
            sum += __shfl_xor_sync(0xffffffffu, sum, 2);
            if ((lane & 3) == 0) sm_s[wc * 128 + rl] = sum;
        }
    __syncthreads();
    if (tid < 128)
        g_ps[(size_t)blockIdx.x * NROWS + r0 + tid] = sm_s[tid] + sm_s[128 + tid];
}

// ---------------- kernel 3: combine + loss (64 blocks, atomic) ----------------
__global__ __launch_bounds__(512)
void k_fin(const float* __restrict__ wp, const float* __restrict__ bp) {
    int row = blockIdx.x * 512 + threadIdx.x;
    float wv = *wp, bv = *bp;
    float S = g_ps[row] + g_ps[(size_t)NROWS + row]
            + g_ps[2*(size_t)NROWS + row] + g_ps[3*(size_t)NROWS + row];
    float pos = fmaf(wv, g_cs[row], bv);
    float c = LN2 * __log2f(S) - pos;
    #pragma unroll
    for (int o = 16; o > 0; o >>= 1) c += __shfl_xor_sync(0xffffffffu, c, o);
    __shared__ float rs[16];
    int w = threadIdx.x >> 5, l = threadIdx.x & 31;
    if (l == 0) rs[w] = c;
    __syncthreads();
    if (threadIdx.x == 0) {
        float bsum = 0.f;
        #pragma unroll
        for (int i = 0; i < 16; ++i) bsum += rs[i];
        atomicAdd(&g_loss, (double)bsum);
    }
}

__global__ void k_out(float* __restrict__ out) { out[0] = (float)g_loss; }

// ---------------- launcher ----------------
extern "C" void kernel_launch(void* const* d_in, const int* in_sizes, int n_in,
                              void* d_out, int out_size) {
    const float* X = (const float*)d_in[0];
    const float* w = (const float*)d_in[1];
    const float* b = (const float*)d_in[2];
    float* out = (float*)d_out;

    cudaFuncSetAttribute(k_gemm, cudaFuncAttributeMaxDynamicSharedMemorySize, SMEM_DYN);

    k_prep<<<NS, 256>>>(X);
    k_gemm<<<dim3(NSPLIT, NROWS / BM), 256, SMEM_DYN>>>(w, b);
    k_fin<<<NROWS / 512, 512>>>(w, b);
    k_out<<<1, 1>>>(out);
}

// round 12
// speedup vs baseline: 1.8057x; 1.8057x over previous
#include <cuda_runtime.h>
#include <cuda_bf16.h>
#include <cuda_fp8.h>
#include <stdint.h>

#define NS     512
#define NU     64
#define DIM    1024
#define NROWS  (NS*NU)         // 32768
#define EPSV   1e-6f
#define BM     128
#define BN     128
#define NSPLIT (NS/BN)         // 4
#define KC     128
#define NSTAGE (DIM/KC)        // 8
#define STG_BYTES 32768        // A 16KB + B 16KB
#define NBUF   3
#define LOG2E  1.4426950408889634f
#define LN2    0.6931471805599453f
#define SMEM_DYN (NBUF*STG_BYTES + 1024 + 2048)

// ---------------- device scratch ----------------
// stage-major, PRE-SWIZZLED (SW128) fp8 operands: one contiguous 16KB tile
// per (stage, 128-row block) -> single cp.async.bulk per operand per stage.
__device__ uint8_t g_A8s[(size_t)NSTAGE*NROWS*KC];  // 32 MB
__device__ uint8_t g_C8s[(size_t)NSTAGE*NS*KC];     // 512 KB
__device__ float  g_cs[NROWS];                      // cos_self (exact fp32)
__device__ float  g_ps[NSPLIT*(size_t)NROWS];       // partial softmax sums
__device__ double g_loss;

// ---------------- helpers ----------------
__device__ __forceinline__ uint32_t smem_u32(const void* p) {
    uint32_t a;
    asm("{ .reg .u64 t; cvta.to.shared.u64 t, %1; cvt.u32.u64 %0, t; }"
        : "=r"(a) : "l"(p));
    return a;
}
__device__ __forceinline__ uint32_t sw128(uint32_t off) {
    return off ^ ((off >> 3) & 0x70);
}
#define BULK_G2S(dst, src, bytes, mbar) \
    asm volatile("cp.async.bulk.shared::cluster.global.mbarrier::complete_tx::bytes " \
                 "[%0], [%1], %2, [%3];" \
                 :: "r"(dst), "l"(src), "r"(bytes), "r"(mbar) : "memory")
#define MBAR_INIT(mb, cnt) \
    asm volatile("mbarrier.init.shared.b64 [%0], %1;" :: "r"(mb), "r"(cnt) : "memory")
#define MBAR_EXPECT_TX(mb, tx) \
    asm volatile("mbarrier.arrive.expect_tx.shared.b64 _, [%0], %1;" \
                 :: "r"(mb), "r"(tx) : "memory")
#define MBAR_WAIT(mb, ph) do { \
    uint32_t _m = (mb), _p = (ph), _d; \
    asm volatile("{\n\t.reg .pred p;\n\t" \
        "mbarrier.try_wait.parity.shared.b64 p, [%1], %2;\n\t" \
        "selp.b32 %0, 1, 0, p;\n\t}" : "=r"(_d) : "r"(_m), "r"(_p) : "memory"); \
    if (!_d) { \
        asm volatile("{\n\t.reg .pred P1;\n\tWL%=:\n\t" \
            "mbarrier.try_wait.parity.shared.b64 P1, [%0], %1;\n\t" \
            "@P1 bra.uni WD%=;\n\tbra.uni WL%=;\n\tWD%=:\n\t}" \
            :: "r"(_m), "r"(_p) : "memory"); \
    } } while (0)
#define LDSM4(r0, r1, r2, r3, addr) \
    asm volatile("ldmatrix.sync.aligned.m8n8.x4.shared.b16 {%0,%1,%2,%3}, [%4];" \
        : "=r"(r0), "=r"(r1), "=r"(r2), "=r"(r3) : "r"(addr))
#define MMA8(c, a, b0, b1) \
    asm volatile("mma.sync.aligned.m16n8k32.row.col.f32.e4m3.e4m3.f32 " \
        "{%0,%1,%2,%3},{%4,%5,%6,%7},{%8,%9},{%0,%1,%2,%3};" \
        : "+f"((c)[0]), "+f"((c)[1]), "+f"((c)[2]), "+f"((c)[3]) \
        : "r"((a)[0]), "r"((a)[1]), "r"((a)[2]), "r"((a)[3]), "r"(b0), "r"(b1))

// FMA-only 2^z (no MUFU): rel err ~2e-6
__device__ __forceinline__ float exp2_fast(float z) {
    float kf = z + 12582912.0f;            // 1.5 * 2^23
    int   ki = __float_as_int(kf);
    float f  = z - (kf - 12582912.0f);     // f in [-0.5, 0.5]
    float p  = 1.33335581e-3f;
    p = fmaf(p, f, 9.61812910e-3f);
    p = fmaf(p, f, 5.55041087e-2f);
    p = fmaf(p, f, 2.40226507e-1f);
    p = fmaf(p, f, 6.93147181e-1f);
    p = fmaf(p, f, 1.0f);
    return __int_as_float(__float_as_int(p) + (ki << 23));
}

__device__ __forceinline__ uint32_t fp8x4(float4 v) {
    __nv_fp8x4_e4m3 r(v);
    return *(uint32_t*)&r;
}

// ---------------- kernel 1: centroids + row stats + fp8 quant (pre-swizzled)
// grid 512 (one speaker), 256 threads. (no launch_bounds cap: 80 regs, no spills)
__global__ void k_prep(const float* __restrict__ X) {
    __shared__ float smS[DIM];
    __shared__ float red[256];
    int n = blockIdx.x, t = threadIdx.x;
    if (n == 0 && t == 0) g_loss = 0.0;
    const float4* xn = (const float4*)(X + (size_t)n * NU * DIM);

    // ---- phase 1: accumulate speaker sum S (2 chains for MLP) ----
    float4 sa = make_float4(0.f, 0.f, 0.f, 0.f);
    float4 sb = make_float4(0.f, 0.f, 0.f, 0.f);
    #pragma unroll 8
    for (int m = 0; m < NU; m += 2) {
        float4 va = xn[m * 256 + t];
        float4 vb = xn[(m + 1) * 256 + t];
        sa.x += va.x; sa.y += va.y; sa.z += va.z; sa.w += va.w;
        sb.x += vb.x; sb.y += vb.y; sb.z += vb.z; sb.w += vb.w;
    }
    float4 s = make_float4(sa.x + sb.x, sa.y + sb.y, sa.z + sb.z, sa.w + sb.w);
    float4 mn = make_float4(s.x * (1.f/NU), s.y * (1.f/NU),
                            s.z * (1.f/NU), s.w * (1.f/NU));
    float ssl = mn.x*mn.x + mn.y*mn.y + mn.z*mn.z + mn.w*mn.w;
    red[t] = ssl;
    ((float4*)smS)[t] = s;
    __syncthreads();
    for (int o = 128; o > 0; o >>= 1) { if (t < o) red[t] += red[t + o]; __syncthreads(); }
    float inv = rsqrtf(fmaxf(red[0], EPSV));
    float SS = red[0] * 4096.f;                       // ||S||^2 exact

    // centroid fp8, stage-major + swizzled: stage = t>>5, chunk byte = 4*(t&31)
    {
        float sc = 16.f * inv;
        uint32_t pk = fp8x4(make_float4(mn.x*sc, mn.y*sc, mn.z*sc, mn.w*sc));
        size_t off = (size_t)(t >> 5) * (NS * (size_t)KC)
                   + sw128((uint32_t)n * 128u + 4u * (t & 31));
        *(uint32_t*)(g_C8s + off) = pk;
    }

    // ---- phase 2: per-row stats + quantized write (stage-major, swizzled) --
    int wid = t >> 5, lane = t & 31;
    #pragma unroll 1
    for (int r = 0; r < 8; ++r) {
        int m = wid * 8 + r;
        const float4* x = xn + m * 256;
        float4 v[8];
        float rx = 0.f, rs = 0.f;
        #pragma unroll
        for (int q = 0; q < 8; ++q) {
            v[q] = x[lane + 32 * q];
            float4 c = ((const float4*)smS)[lane + 32 * q];
            rx += v[q].x*v[q].x + v[q].y*v[q].y + v[q].z*v[q].z + v[q].w*v[q].w;
            rs += v[q].x*c.x + v[q].y*c.y + v[q].z*c.z + v[q].w*c.w;
        }
        #pragma unroll
        for (int o = 16; o > 0; o >>= 1) {
            rx += __shfl_xor_sync(0xffffffffu, rx, o);
            rs += __shfl_xor_sync(0xffffffffu, rs, o);
        }
        float inv_e = rsqrtf(fmaxf(rx, EPSV));
        int row = n * NU + m;
        if (lane == 0) {
            float xu = (rs - rx) * (1.f / 63.f);
            float uu = (SS - 2.f * rs + rx) * (1.f / 3969.f);
            g_cs[row] = xu * inv_e * rsqrtf(fmaxf(uu, EPSV));
        }
        float qs = 16.f * inv_e;
        uint32_t swoff = sw128((uint32_t)row * 128u + 4u * lane);
        #pragma unroll
        for (int q = 0; q < 8; ++q) {
            size_t off = (size_t)q * ((size_t)NROWS * KC) + swoff;
            *(uint32_t*)(g_A8s + off) =
                fp8x4(make_float4(v[q].x*qs, v[q].y*qs, v[q].z*qs, v[q].w*qs));
        }
    }
}

// ---------------- kernel 2: fp8 MMA GEMM, bulk pipeline (R10 config) --------
// grid (4, 256): x = col-split (128 cols), y = row-block (128 rows).
// 256 threads / 8 warps: 4 row-groups x 2 col-groups, warp tile 32x64.
__global__ __launch_bounds__(256, 2)
void k_gemm(const float* __restrict__ wp, const float* __restrict__ bp) {
    extern __shared__ char smraw[];
    __shared__ __align__(8) uint64_t mbars[NBUF];
    uint32_t raw  = smem_u32(smraw);
    uint32_t base = (raw + 1023u) & ~1023u;
    float* sm_s   = (float*)(smraw + (base - raw) + NBUF * STG_BYTES);
    uint32_t mb0  = smem_u32(mbars);

    int tid = threadIdx.x, lane = tid & 31, wid = tid >> 5;
    int wr = wid & 3, wc = wid >> 2;      // 4 row-groups x 2 col-groups
    int c0 = blockIdx.x * BN, r0 = blockIdx.y * BM;

    if (tid == 0) {
        MBAR_INIT(mb0,      1);
        MBAR_INIT(mb0 + 8,  1);
        MBAR_INIT(mb0 + 16, 1);
    }
    __syncthreads();

    float acc[2][8][4];
    #pragma unroll
    for (int i = 0; i < 2; ++i)
        #pragma unroll
        for (int j = 0; j < 8; ++j)
            #pragma unroll
            for (int q = 0; q < 4; ++q) acc[i][j][q] = 0.f;

    const char* abase = (const char*)g_A8s + (size_t)r0 * KC;
    const char* bbase = (const char*)g_C8s + (size_t)c0 * KC;

    auto load_stage = [&](int s) {
        int buf = s % NBUF;
        uint32_t mb = mb0 + 8u * (uint32_t)buf;
        uint32_t sb = base + (uint32_t)buf * STG_BYTES;
        MBAR_EXPECT_TX(mb, STG_BYTES);
        BULK_G2S(sb,          abase + (size_t)s * ((size_t)NROWS * KC), 16384u, mb);
        BULK_G2S(sb + 16384u, bbase + (size_t)s * ((size_t)NS * KC),    16384u, mb);
    };

    // ---- mma over one staged KC=128 slab (4 x k32 steps) ----
    auto mma_stage = [&](int buf) {
        uint32_t ab = base + (uint32_t)buf * STG_BYTES;
        uint32_t bb = ab + 16384u;
        int arow = wr * 32 + (lane & 15);
        uint32_t aX = (uint32_t)(arow & 7) * 16u;
        uint32_t arb = ab + (uint32_t)arow * 128u;
        int nrl = wc * 64 + (lane & 7) + ((lane >> 4) << 3);
        uint32_t bX = (uint32_t)(nrl & 7) * 16u;
        uint32_t brb = bb + (uint32_t)nrl * 128u;
        #pragma unroll
        for (int ks = 0; ks < 4; ++ks) {
            uint32_t acb = ((uint32_t)(ks * 32 + ((lane >> 4) << 4))) ^ aX;
            uint32_t bcb = ((uint32_t)(ks * 32 + (((lane >> 3) & 1) << 4))) ^ bX;
            uint32_t a[2][4];
            LDSM4(a[0][0], a[0][1], a[0][2], a[0][3], arb + acb);
            LDSM4(a[1][0], a[1][1], a[1][2], a[1][3], arb + 16u * 128u + acb);
            #pragma unroll
            for (int g = 0; g < 4; ++g) {
                uint32_t b0, b1, b2, b3;
                LDSM4(b0, b1, b2, b3, brb + (uint32_t)g * (16u * 128u) + bcb);
                MMA8(acc[0][2 * g    ], a[0], b0, b1);
                MMA8(acc[0][2 * g + 1], a[0], b2, b3);
                MMA8(acc[1][2 * g    ], a[1], b0, b1);
                MMA8(acc[1][2 * g + 1], a[1], b2, b3);
            }
        }
    };

    // ---- 3-buffer bulk pipeline (lookahead 2) ----
    if (tid == 0) { load_stage(0); load_stage(1); }
    for (int s = 0; s < NSTAGE; ++s) {
        MBAR_WAIT(mb0 + 8u * (uint32_t)(s % NBUF), (s / NBUF) & 1);
        __syncthreads();           // all warps done with mma(s-1) and past wait
        if (tid == 0 && s + 2 < NSTAGE) load_stage(s + 2);
        mma_stage(s % NBUF);
    }
    __syncthreads();

    // ---- epilogue: base-2 softmax partial sums; cos = acc / 256 ----
    const float wv = *wp, bv = *bp;
    const float b2 = bv * LOG2E;
    const float scal2 = wv * LOG2E * (1.f / 256.f);
    #pragma unroll
    for (int mi = 0; mi < 2; ++mi)
        #pragma unroll
        for (int h = 0; h < 2; ++h) {
            int rl = wr * 32 + mi * 16 + (lane >> 2) + h * 8;
            int grow = r0 + rl, nself = grow >> 6;
            float zpos = fmaf(wv * LOG2E, g_cs[grow], b2);
            float sum = 0.f;
            #pragma unroll
            for (int ni = 0; ni < 8; ++ni)
                #pragma unroll
                for (int j = 0; j < 2; ++j) {
                    int cg = c0 + wc * 64 + ni * 8 + (lane & 3) * 2 + j;
                    float z = fmaf(acc[mi][ni][h * 2 + j], scal2, b2);
                    if (cg == nself) z = zpos;
                    sum += exp2_fast(z);
                }
            sum += __shfl_xor_sync(0xffffffffu, sum, 1);
            sum += __shfl_xor_sync(0xffffffffu, sum, 2);
            if ((lane & 3) == 0) sm_s[wc * 128 + rl] = sum;
        }
    __syncthreads();
    if (tid < 128)
        g_ps[(size_t)blockIdx.x * NROWS + r0 + tid] = sm_s[tid] + sm_s[128 + tid];
}

// ---------------- kernel 3: combine + loss (64 blocks, atomic) --------------
__global__ __launch_bounds__(512)
void k_fin(const float* __restrict__ wp, const float* __restrict__ bp) {
    int row = blockIdx.x * 512 + threadIdx.x;
    float wv = *wp, bv = *bp;
    float S = g_ps[row] + g_ps[(size_t)NROWS + row]
            + g_ps[2*(size_t)NROWS + row] + g_ps[3*(size_t)NROWS + row];
    float pos = fmaf(wv, g_cs[row], bv);
    float c = LN2 * __log2f(S) - pos;
    #pragma unroll
    for (int o = 16; o > 0; o >>= 1) c += __shfl_xor_sync(0xffffffffu, c, o);
    __shared__ float rs[16];
    int w = threadIdx.x >> 5, l = threadIdx.x & 31;
    if (l == 0) rs[w] = c;
    __syncthreads();
    if (threadIdx.x == 0) {
        float bsum = 0.f;
        #pragma unroll
        for (int i = 0; i < 16; ++i) bsum += rs[i];
        atomicAdd(&g_loss, (double)bsum);
    }
}

__global__ void k_out(float* __restrict__ out) { out[0] = (float)g_loss; }

// ---------------- launcher ----------------
extern "C" void kernel_launch(void* const* d_in, const int* in_sizes, int n_in,
                              void* d_out, int out_size) {
    const float* X = (const float*)d_in[0];
    const float* w = (const float*)d_in[1];
    const float* b = (const float*)d_in[2];
    float* out = (float*)d_out;

    cudaFuncSetAttribute(k_gemm, cudaFuncAttributeMaxDynamicSharedMemorySize, SMEM_DYN);

    k_prep<<<NS, 256>>>(X);
    k_gemm<<<dim3(NSPLIT, NROWS / BM), 256, SMEM_DYN>>>(w, b);
    k_fin<<<NROWS / 512, 512>>>(w, b);
    k_out<<<1, 1>>>(out);
}